// round 7
// baseline (speedup 1.0000x reference)
#include <cuda_runtime.h>
#include <cuda_pipeline_primitives.h>

#define BB 4
#define NN 1024
#define INF 256
#define OUTF 256
#define NH 8
#define BN (BB*NN)

// ---------------- scratch (allocation-free) ----------------
__device__ float g_buf[BN*OUTF];    // g = h @ W  (4 MB)
__device__ float p1_buf[BN*OUTF];   // j-half-1 partial output (4 MB)
__device__ float ELraw[BN*NH];
__device__ float ERraw[BN*NH];
__device__ float Lbuf[BN*16];       // [exp(el) x8, exp(.2el) x8]
__device__ float Rbuf[BN*16];       // [exp(er) x8, exp(.2er) x8]
__device__ float c_buf[BN*NH];      // 1/s[b,j,h]
__device__ float4 Rv_glob[BN*NH];   // (Rp*c, Rn*c, c, 0) per (b,j,h)

typedef unsigned long long u64;

__device__ __forceinline__ u64 pack2(float v) {
    u64 r; asm("mov.b64 %0, {%1, %1};" : "=l"(r) : "f"(v)); return r;
}
__device__ __forceinline__ void ffma2(u64& d, u64 a, u64 b) {
    asm("fma.rn.f32x2 %0, %1, %2, %0;" : "+l"(d) : "l"(a), "l"(b));
}
__device__ __forceinline__ u64 fadd2(u64 a, u64 b) {
    u64 r; asm("add.rn.f32x2 %0, %1, %2;" : "=l"(r) : "l"(a), "l"(b)); return r;
}
union U2 { u64 u; float2 f; };

// ---------------------------------------------------------------------------
// K1: g = X @ W, 64x64 tile, 4x4 micro-tile, f32x2, fused el/er epilogue.
// ---------------------------------------------------------------------------
__global__ __launch_bounds__(256) void k_gemm(const float* __restrict__ X,
                                              const float* __restrict__ W,
                                              const float* __restrict__ aw) {
    __shared__ __align__(16) float2 Xs2[16][64];
    __shared__ __align__(16) float  Ws [16][64];
    const int t = threadIdx.x;
    const int row0 = (blockIdx.x >> 2) * 64;
    const int cb   = (blockIdx.x & 3) * 64;
    const int tx = t & 15, ty = t >> 4;
    const int r0 = ty * 4, c0 = tx * 4;

    u64 acc[4][2];
#pragma unroll
    for (int r = 0; r < 4; r++) { acc[r][0] = 0ull; acc[r][1] = 0ull; }

    const int lr = t >> 2, lk4 = (t & 3) * 4;
    const int wk = t >> 4, wc = (t & 15) * 4;

    for (int k0 = 0; k0 < INF; k0 += 16) {
        float4 xv = *reinterpret_cast<const float4*>(&X[(row0 + lr) * INF + k0 + lk4]);
        float4 wv = *reinterpret_cast<const float4*>(&W[(k0 + wk) * OUTF + cb + wc]);
        __syncthreads();
        Xs2[lk4 + 0][lr] = make_float2(xv.x, xv.x);
        Xs2[lk4 + 1][lr] = make_float2(xv.y, xv.y);
        Xs2[lk4 + 2][lr] = make_float2(xv.z, xv.z);
        Xs2[lk4 + 3][lr] = make_float2(xv.w, xv.w);
        *reinterpret_cast<float4*>(&Ws[wk][wc]) = wv;
        __syncthreads();
#pragma unroll
        for (int kk = 0; kk < 16; kk++) {
            const ulonglong2* xp = reinterpret_cast<const ulonglong2*>(&Xs2[kk][r0]);
            ulonglong2 xa = xp[0], xb = xp[1];
            ulonglong2 wv2 = *reinterpret_cast<const ulonglong2*>(&Ws[kk][c0]);
            ffma2(acc[0][0], xa.x, wv2.x); ffma2(acc[0][1], xa.x, wv2.y);
            ffma2(acc[1][0], xa.y, wv2.x); ffma2(acc[1][1], xa.y, wv2.y);
            ffma2(acc[2][0], xb.x, wv2.x); ffma2(acc[2][1], xb.x, wv2.y);
            ffma2(acc[3][0], xb.y, wv2.x); ffma2(acc[3][1], xb.y, wv2.y);
        }
    }

    const float4* awp = reinterpret_cast<const float4*>(aw);
    float4 aL = awp[tx & 7];
    float4 aR = awp[8 + (tx & 7)];

#pragma unroll
    for (int r = 0; r < 4; r++) {
        U2 a, b; a.u = acc[r][0]; b.u = acc[r][1];
        float4 o = make_float4(a.f.x, a.f.y, b.f.x, b.f.y);
        *reinterpret_cast<float4*>(&g_buf[(row0 + r0 + r) * OUTF + cb + c0]) = o;

        float el = o.x*aL.x + o.y*aL.y + o.z*aL.z + o.w*aL.w;
        float er = o.x*aR.x + o.y*aR.y + o.z*aR.z + o.w*aR.w;
        el += __shfl_xor_sync(0xffffffffu, el, 1);
        el += __shfl_xor_sync(0xffffffffu, el, 2);
        el += __shfl_xor_sync(0xffffffffu, el, 4);
        er += __shfl_xor_sync(0xffffffffu, er, 1);
        er += __shfl_xor_sync(0xffffffffu, er, 2);
        er += __shfl_xor_sync(0xffffffffu, er, 4);
        if ((tx & 7) == 0) {
            int head = (cb >> 5) + (tx >> 3);
            int row = row0 + r0 + r;
            ELraw[row * NH + head] = el;
            ERraw[row * NH + head] = er;
        }
    }
}

// ---------------------------------------------------------------------------
__global__ __launch_bounds__(256) void k_exp() {
    int idx = blockIdx.x * 256 + threadIdx.x;
    int row = idx >> 3, h = idx & 7;
    float el = ELraw[idx], er = ERraw[idx];
    Lbuf[row * 16 + h]     = __expf(el);
    Lbuf[row * 16 + 8 + h] = __expf(0.2f * el);
    Rbuf[row * 16 + h]     = __expf(er);
    Rbuf[row * 16 + 8 + h] = __expf(0.2f * er);
}

// ---------------------------------------------------------------------------
// K2: c[b,j,h] = 1 / sum_i adj[b,i,j]*wexp(i,j,h); also writes Rv_glob.
// ---------------------------------------------------------------------------
__global__ __launch_bounds__(512) void k_c(const float* __restrict__ adj) {
    __shared__ float ssum[16][32][8];
    const int t = threadIdx.x;
    const int b = blockIdx.x >> 5;
    const int j0 = (blockIdx.x & 31) * 32;
    const int jl = t & 31, ig = t >> 5;

    const float4* rrow = reinterpret_cast<const float4*>(&Rbuf[(b * NN + j0 + jl) * 16]);
    float4 rp0 = rrow[0], rp1 = rrow[1], rn0 = rrow[2], rn1 = rrow[3];
    float EPr[8] = {rp0.x, rp0.y, rp0.z, rp0.w, rp1.x, rp1.y, rp1.z, rp1.w};
    float ENr[8] = {rn0.x, rn0.y, rn0.z, rn0.w, rn1.x, rn1.y, rn1.z, rn1.w};

    float acc[8];
#pragma unroll
    for (int h = 0; h < 8; h++) acc[h] = 0.f;

    const float* adjcol = adj + (size_t)b * NN * NN + j0 + jl;
#pragma unroll 4
    for (int i = ig; i < NN; i += 16) {
        float a = __ldg(adjcol + (size_t)i * NN);
        const float4* lr = reinterpret_cast<const float4*>(&Lbuf[(b * NN + i) * 16]);
        float4 lp0 = __ldg(&lr[0]), lp1 = __ldg(&lr[1]);
        float4 ln0 = __ldg(&lr[2]), ln1 = __ldg(&lr[3]);
        float EPl[8] = {lp0.x, lp0.y, lp0.z, lp0.w, lp1.x, lp1.y, lp1.z, lp1.w};
        float ENl[8] = {ln0.x, ln0.y, ln0.z, ln0.w, ln1.x, ln1.y, ln1.z, ln1.w};
#pragma unroll
        for (int h = 0; h < 8; h++) {
            float p = EPl[h] * EPr[h];
            float q = ENl[h] * ENr[h];
            float w = (p >= 1.0f) ? p : q;
            acc[h] = fmaf(a, w, acc[h]);
        }
    }
#pragma unroll
    for (int h = 0; h < 8; h++) ssum[ig][jl][h] = acc[h];
    __syncthreads();

    if (t < 256) {
        int jl2 = t >> 3, h = t & 7;
        float s = 0.f;
#pragma unroll
        for (int g = 0; g < 16; g++) s += ssum[g][jl2][h];
        float cc = 1.0f / s;
        int row = b * NN + j0 + jl2;
        c_buf[row * NH + h] = cc;
        float Rp = Rbuf[row * 16 + h] * cc;
        float Rn = Rbuf[row * 16 + 8 + h] * cc;
        Rv_glob[row * NH + h] = make_float4(Rp, Rn, cc, 0.f);
    }
}

// ---------------------------------------------------------------------------
// K3: partial[b,i,h,:] = sum_{j in half} adj*wexp*c[j,h] * g[b,j,h,:]
// Grid 256 = (j-half, b, 32-row i tile), 256 thr = 8 warps = 8 heads,
// 2 blocks/SM. cp.async double-buffers g/adj (latency off critical path);
// Wgt is warp-private (h) -> only __syncwarp between weight phase and sweep.
// Thread tile 8 il x 8 d, lane parity splits jj: 1.0 B/FMA.
// ---------------------------------------------------------------------------
struct SmemAgg {
    float4 Gs4[2][32][64];     // g tiles (double-buffered)      64 KB
    float  adj_s[2][32][33];   // adj tiles (padded rows)        8.4 KB
    float  Wgt[8][32][36];     // [h][jj][il] (16B-aligned pad)  36.9 KB
    float  Ltile[32][16];      //                                2 KB
};

__device__ __forceinline__ void stage_chunk(SmemAgg& sm, const float* adj,
                                            const float4* g4, int b, int i0,
                                            int j0, int buf, int t) {
#pragma unroll
    for (int m = 0; m < 8; m++) {
        int v = t + m * 256;
        int jj = v >> 6, c4 = v & 63;
        __pipeline_memcpy_async(&sm.Gs4[buf][jj][c4],
                                &g4[(size_t)(b * NN + j0 + jj) * 64 + c4], 16);
    }
#pragma unroll
    for (int m = 0; m < 4; m++) {
        int idx = t + m * 256;
        int il = idx >> 5, jj = idx & 31;
        __pipeline_memcpy_async(&sm.adj_s[buf][il][jj],
                                &adj[(size_t)(b * NN + i0 + il) * NN + j0 + jj], 4);
    }
}

__global__ __launch_bounds__(256, 2) void k_agg(const float* __restrict__ adj,
                                                float* __restrict__ out) {
    extern __shared__ char smraw[];
    SmemAgg& sm = *reinterpret_cast<SmemAgg*>(smraw);
    const int t = threadIdx.x;
    const int bid = blockIdx.x;
    const int half = bid >> 7;
    const int b = (bid >> 5) & 3;
    const int i0 = (bid & 31) * 32;
    float* dst = half ? p1_buf : out;

    {   // stage Ltile (plain loads, covered by first barrier)
#pragma unroll
        for (int m = 0; m < 2; m++) {
            int idx = t + m * 256;
            int il = idx >> 4, c = idx & 15;
            sm.Ltile[il][c] = Lbuf[(b * NN + i0 + il) * 16 + c];
        }
    }

    const int l   = t & 31;
    const int h   = t >> 5;            // warp = head
    const int par = l & 1;             // jj parity
    const int ilg = (l >> 1) & 3;      // il group: il = 8*ilg..+7
    const int q   = l >> 3;            // d group: d = 8q..+7

    u64 acc[8][4];
#pragma unroll
    for (int r = 0; r < 8; r++)
#pragma unroll
        for (int c = 0; c < 4; c++) acc[r][c] = 0ull;

    const float4* g4 = reinterpret_cast<const float4*>(g_buf);
    const int jstart = half * 512;

    // prologue: stage chunk 0 into buf 0
    stage_chunk(sm, adj, g4, b, i0, jstart, 0, t);
    __pipeline_commit();
    __syncthreads();    // Ltile visible
    const float Lp = sm.Ltile[l][h];   // weight-phase values (lane = il)
    const float Ln = sm.Ltile[l][8 + h];

#pragma unroll 1
    for (int n = 0; n < 16; n++) {
        const int j0 = jstart + n * 32;
        const int buf = n & 1;

        // issue next chunk's copies (prev reads of this buffer ended at the
        // barrier that closed iteration n-1's sweep — see sync below)
        if (n < 15) {
            stage_chunk(sm, adj, g4, b, i0, j0 + 32, buf ^ 1, t);
            __pipeline_commit();
            __pipeline_wait_prior(1);   // chunk n's copies complete
        } else {
            __pipeline_wait_prior(0);
        }
        __syncthreads();                // chunk n visible to all threads

        // weight phase: warp h, lane = il; Rv via uniform-broadcast ldg
#pragma unroll 4
        for (int jj = 0; jj < 32; jj++) {
            float4 rv = __ldg(&Rv_glob[(b * NN + j0 + jj) * NH + h]);
            float p  = Lp * rv.x;
            float qn = Ln * rv.y;
            float w  = (p >= rv.z) ? p : qn;
            sm.Wgt[h][jj][l] = sm.adj_s[buf][l][jj] * w;
        }
        __syncwarp();                   // Wgt[h] is warp-private

        // FMA sweep: lane parity takes jj = 2*jj2 + par
#pragma unroll 4
        for (int jj2 = 0; jj2 < 16; jj2++) {
            int jj = 2 * jj2 + par;
            const ulonglong2* gp =
                reinterpret_cast<const ulonglong2*>(&sm.Gs4[buf][jj][h * 8 + 2 * q]);
            ulonglong2 ga = gp[0], gb = gp[1];      // d = 8q..8q+7
            const float4* wp =
                reinterpret_cast<const float4*>(&sm.Wgt[h][jj][8 * ilg]);
            float4 wv0 = wp[0], wv1 = wp[1];        // il 8ilg..8ilg+7
            u64 wd[8];
            wd[0] = pack2(wv0.x); wd[1] = pack2(wv0.y);
            wd[2] = pack2(wv0.z); wd[3] = pack2(wv0.w);
            wd[4] = pack2(wv1.x); wd[5] = pack2(wv1.y);
            wd[6] = pack2(wv1.z); wd[7] = pack2(wv1.w);
#pragma unroll
            for (int il = 0; il < 8; il++) {
                ffma2(acc[il][0], wd[il], ga.x);
                ffma2(acc[il][1], wd[il], ga.y);
                ffma2(acc[il][2], wd[il], gb.x);
                ffma2(acc[il][3], wd[il], gb.y);
            }
        }
        __syncthreads();   // all warps done reading buf before it is re-staged
    }

    // parity reduction: lane xor 1, then par==0 lanes store
#pragma unroll
    for (int r = 0; r < 8; r++)
#pragma unroll
        for (int c = 0; c < 4; c++) {
            u64 o = __shfl_xor_sync(0xffffffffu, acc[r][c], 1);
            acc[r][c] = fadd2(acc[r][c], o);
        }

    if (par == 0) {
        float4* out4 = reinterpret_cast<float4*>(dst);
#pragma unroll
        for (int il = 0; il < 8; il++) {
            U2 a0, a1, a2, a3;
            a0.u = acc[il][0]; a1.u = acc[il][1];
            a2.u = acc[il][2]; a3.u = acc[il][3];
            int i = i0 + 8 * ilg + il;
            size_t base = (size_t)(b * NN + i) * 64 + h * 8 + 2 * q;
            out4[base]     = make_float4(a0.f.x, a0.f.y, a1.f.x, a1.f.y);
            out4[base + 1] = make_float4(a2.f.x, a2.f.y, a3.f.x, a3.f.y);
        }
    }
}

// ---------------------------------------------------------------------------
// K4: out += p1   (combine j-halves)
// ---------------------------------------------------------------------------
__global__ __launch_bounds__(256) void k_comb(float* __restrict__ out) {
    int idx = blockIdx.x * 256 + threadIdx.x;    // < BN*OUTF/4
    float4* o4 = reinterpret_cast<float4*>(out);
    const float4* p4 = reinterpret_cast<const float4*>(p1_buf);
    float4 a = o4[idx], b = p4[idx];
    o4[idx] = make_float4(a.x + b.x, a.y + b.y, a.z + b.z, a.w + b.w);
}

// ---------------------------------------------------------------------------
extern "C" void kernel_launch(void* const* d_in, const int* in_sizes, int n_in,
                              void* d_out, int out_size) {
    const float* h_in = (const float*)d_in[0];
    const float* adj  = (const float*)d_in[1];
    const float* W    = (const float*)d_in[2];
    const float* aw   = (const float*)d_in[3];
    float* out = (float*)d_out;

    static bool attr_set = false;
    if (!attr_set) {
        cudaFuncSetAttribute(k_agg, cudaFuncAttributeMaxDynamicSharedMemorySize,
                             (int)sizeof(SmemAgg));
        attr_set = true;
    }

    k_gemm<<<256, 256>>>(h_in, W, aw);
    k_exp<<<BN * NH / 256, 256>>>();
    k_c<<<(BB * NN) / 32, 512>>>(adj);
    k_agg<<<256, 256, sizeof(SmemAgg)>>>(adj, out);
    k_comb<<<BN * OUTF / 4 / 256, 256>>>(out);
}

// round 9
// speedup vs baseline: 1.0550x; 1.0550x over previous
#include <cuda_runtime.h>
#include <cstdint>

#define BB 4
#define NN 1024
#define INF 256
#define OUTF 256
#define NH 8
#define BN (BB*NN)

// ---------------- scratch (allocation-free) ----------------
__device__ float g_buf[BN*OUTF];    // g = h @ W  (4 MB)
__device__ float ELraw[BN*NH];
__device__ float ERraw[BN*NH];
__device__ float Lbuf[BN*16];       // [exp(el) x8, exp(.2el) x8]
__device__ float Rbuf[BN*16];       // [exp(er) x8, exp(.2er) x8]
__device__ float4 Rv_glob[BN*NH];   // (Rp*c, Rn*c, c, 0) per (b,j,h)

typedef unsigned long long u64;

__device__ __forceinline__ void ffma2(u64& d, u64 a, u64 b) {
    asm("fma.rn.f32x2 %0, %1, %2, %0;" : "+l"(d) : "l"(a), "l"(b));
}
union U2 { u64 u; float2 f; };

__device__ __forceinline__ uint32_t f2tf32(float f) {
    uint32_t r; asm("cvt.rna.tf32.f32 %0, %1;" : "=r"(r) : "f"(f)); return r;
}
// D += A*B (m16n8k8 tf32, row.col)
__device__ __forceinline__ void mma_tf32(float* d, const uint32_t* a,
                                         const uint32_t* b) {
    asm volatile(
        "mma.sync.aligned.m16n8k8.row.col.f32.tf32.tf32.f32 "
        "{%0,%1,%2,%3}, {%4,%5,%6,%7}, {%8,%9}, {%0,%1,%2,%3};"
        : "+f"(d[0]), "+f"(d[1]), "+f"(d[2]), "+f"(d[3])
        : "r"(a[0]), "r"(a[1]), "r"(a[2]), "r"(a[3]), "r"(b[0]), "r"(b[1]));
}

// ---------------------------------------------------------------------------
// K1: g = X @ W, 64x64 tile, 4x4 micro-tile, f32x2, fused el/er epilogue.
// ---------------------------------------------------------------------------
__global__ __launch_bounds__(256) void k_gemm(const float* __restrict__ X,
                                              const float* __restrict__ W,
                                              const float* __restrict__ aw) {
    __shared__ __align__(16) float2 Xs2[16][64];
    __shared__ __align__(16) float  Ws [16][64];
    const int t = threadIdx.x;
    const int row0 = (blockIdx.x >> 2) * 64;
    const int cb   = (blockIdx.x & 3) * 64;
    const int tx = t & 15, ty = t >> 4;
    const int r0 = ty * 4, c0 = tx * 4;

    u64 acc[4][2];
#pragma unroll
    for (int r = 0; r < 4; r++) { acc[r][0] = 0ull; acc[r][1] = 0ull; }

    const int lr = t >> 2, lk4 = (t & 3) * 4;
    const int wk = t >> 4, wc = (t & 15) * 4;

    for (int k0 = 0; k0 < INF; k0 += 16) {
        float4 xv = *reinterpret_cast<const float4*>(&X[(row0 + lr) * INF + k0 + lk4]);
        float4 wv = *reinterpret_cast<const float4*>(&W[(k0 + wk) * OUTF + cb + wc]);
        __syncthreads();
        Xs2[lk4 + 0][lr] = make_float2(xv.x, xv.x);
        Xs2[lk4 + 1][lr] = make_float2(xv.y, xv.y);
        Xs2[lk4 + 2][lr] = make_float2(xv.z, xv.z);
        Xs2[lk4 + 3][lr] = make_float2(xv.w, xv.w);
        *reinterpret_cast<float4*>(&Ws[wk][wc]) = wv;
        __syncthreads();
#pragma unroll
        for (int kk = 0; kk < 16; kk++) {
            const ulonglong2* xp = reinterpret_cast<const ulonglong2*>(&Xs2[kk][r0]);
            ulonglong2 xa = xp[0], xb = xp[1];
            ulonglong2 wv2 = *reinterpret_cast<const ulonglong2*>(&Ws[kk][c0]);
            ffma2(acc[0][0], xa.x, wv2.x); ffma2(acc[0][1], xa.x, wv2.y);
            ffma2(acc[1][0], xa.y, wv2.x); ffma2(acc[1][1], xa.y, wv2.y);
            ffma2(acc[2][0], xb.x, wv2.x); ffma2(acc[2][1], xb.x, wv2.y);
            ffma2(acc[3][0], xb.y, wv2.x); ffma2(acc[3][1], xb.y, wv2.y);
        }
    }

    const float4* awp = reinterpret_cast<const float4*>(aw);
    float4 aL = awp[tx & 7];
    float4 aR = awp[8 + (tx & 7)];

#pragma unroll
    for (int r = 0; r < 4; r++) {
        U2 a, b; a.u = acc[r][0]; b.u = acc[r][1];
        float4 o = make_float4(a.f.x, a.f.y, b.f.x, b.f.y);
        *reinterpret_cast<float4*>(&g_buf[(row0 + r0 + r) * OUTF + cb + c0]) = o;

        float el = o.x*aL.x + o.y*aL.y + o.z*aL.z + o.w*aL.w;
        float er = o.x*aR.x + o.y*aR.y + o.z*aR.z + o.w*aR.w;
        el += __shfl_xor_sync(0xffffffffu, el, 1);
        el += __shfl_xor_sync(0xffffffffu, el, 2);
        el += __shfl_xor_sync(0xffffffffu, el, 4);
        er += __shfl_xor_sync(0xffffffffu, er, 1);
        er += __shfl_xor_sync(0xffffffffu, er, 2);
        er += __shfl_xor_sync(0xffffffffu, er, 4);
        if ((tx & 7) == 0) {
            int head = (cb >> 5) + (tx >> 3);
            int row = row0 + r0 + r;
            ELraw[row * NH + head] = el;
            ERraw[row * NH + head] = er;
        }
    }
}

// ---------------------------------------------------------------------------
__global__ __launch_bounds__(256) void k_exp() {
    int idx = blockIdx.x * 256 + threadIdx.x;
    int row = idx >> 3, h = idx & 7;
    float el = ELraw[idx], er = ERraw[idx];
    Lbuf[row * 16 + h]     = __expf(el);
    Lbuf[row * 16 + 8 + h] = __expf(0.2f * el);
    Rbuf[row * 16 + h]     = __expf(er);
    Rbuf[row * 16 + 8 + h] = __expf(0.2f * er);
}

// ---------------------------------------------------------------------------
// K2: 1/s[b,j,h]; writes Rv_glob = (Rp*c, Rn*c, c, 0).
// ---------------------------------------------------------------------------
__global__ __launch_bounds__(512) void k_c(const float* __restrict__ adj) {
    __shared__ float ssum[16][32][8];
    const int t = threadIdx.x;
    const int b = blockIdx.x >> 5;
    const int j0 = (blockIdx.x & 31) * 32;
    const int jl = t & 31, ig = t >> 5;

    const float4* rrow = reinterpret_cast<const float4*>(&Rbuf[(b * NN + j0 + jl) * 16]);
    float4 rp0 = rrow[0], rp1 = rrow[1], rn0 = rrow[2], rn1 = rrow[3];
    float EPr[8] = {rp0.x, rp0.y, rp0.z, rp0.w, rp1.x, rp1.y, rp1.z, rp1.w};
    float ENr[8] = {rn0.x, rn0.y, rn0.z, rn0.w, rn1.x, rn1.y, rn1.z, rn1.w};

    float acc[8];
#pragma unroll
    for (int h = 0; h < 8; h++) acc[h] = 0.f;

    const float* adjcol = adj + (size_t)b * NN * NN + j0 + jl;
#pragma unroll 4
    for (int i = ig; i < NN; i += 16) {
        float a = __ldg(adjcol + (size_t)i * NN);
        const float4* lr = reinterpret_cast<const float4*>(&Lbuf[(b * NN + i) * 16]);
        float4 lp0 = __ldg(&lr[0]), lp1 = __ldg(&lr[1]);
        float4 ln0 = __ldg(&lr[2]), ln1 = __ldg(&lr[3]);
        float EPl[8] = {lp0.x, lp0.y, lp0.z, lp0.w, lp1.x, lp1.y, lp1.z, lp1.w};
        float ENl[8] = {ln0.x, ln0.y, ln0.z, ln0.w, ln1.x, ln1.y, ln1.z, ln1.w};
#pragma unroll
        for (int h = 0; h < 8; h++) {
            float p = EPl[h] * EPr[h];
            float q = ENl[h] * ENr[h];
            float w = (p >= 1.0f) ? p : q;
            acc[h] = fmaf(a, w, acc[h]);
        }
    }
#pragma unroll
    for (int h = 0; h < 8; h++) ssum[ig][jl][h] = acc[h];
    __syncthreads();

    if (t < 256) {
        int jl2 = t >> 3, h = t & 7;
        float s = 0.f;
#pragma unroll
        for (int g = 0; g < 16; g++) s += ssum[g][jl2][h];
        float cc = 1.0f / s;
        int row = b * NN + j0 + jl2;
        float Rp = Rbuf[row * 16 + h] * cc;
        float Rn = Rbuf[row * 16 + 8 + h] * cc;
        Rv_glob[row * NH + h] = make_float4(Rp, Rn, cc, 0.f);
    }
}

// ---------------------------------------------------------------------------
// K3 (tensor, mma.sync tf32 + 3xTF32): per (b,h,128-row i-tile):
//   out_tile[128 x 32] = Wgt[128 x 1024] @ G[1024 x 32]
// 256 thr = 8 warps; warp w owns rows 16w..16w+15. Per 32-j chunk:
//  - weight tile -> A_hi/A_lo (tf32 split), stride-36 rows
//  - g transposed -> G_hi/G_lo [d][j], stride-36 rows
//  - 4 kstep x 4 ntile x 3 mma into 16 f32 accums.
// ---------------------------------------------------------------------------
#define ASTR 36
struct SmemT {
    float A_hi[128][ASTR];   // 18.4 KB
    float A_lo[128][ASTR];   // 18.4 KB
    float G_hi[32][ASTR];    //  4.6 KB
    float G_lo[32][ASTR];    //  4.6 KB
    float4 Rv_s[2][32];      //  1 KB
};

__global__ __launch_bounds__(256) void k_aggmma(const float* __restrict__ adj,
                                                float* __restrict__ out) {
    __shared__ SmemT sm;
    const int t = threadIdx.x;
    const int bid = blockIdx.x;
    const int b  = bid >> 6;
    const int h  = (bid >> 3) & 7;
    const int i0 = (bid & 7) * 128;

    // weight-phase role: row il, j-half jh
    const int il = t >> 1, jh = t & 1;
    const float Lp = Lbuf[(b * NN + i0 + il) * 16 + h];
    const float Ln = Lbuf[(b * NN + i0 + il) * 16 + 8 + h];

    // mma-phase role
    const int lane = t & 31, w = t >> 5;
    const int gq = lane >> 2, tid4 = lane & 3;
    const int m0 = w * 16;

    float acc[4][4];
#pragma unroll
    for (int nt = 0; nt < 4; nt++)
#pragma unroll
        for (int c = 0; c < 4; c++) acc[nt][c] = 0.f;

    if (t < 32) sm.Rv_s[0][t] = __ldg(&Rv_glob[(b * NN + t) * NH + h]);
    __syncthreads();

    for (int n = 0; n < 32; n++) {
        const int j0 = n * 32;
        const int rb = n & 1;

        // stage next chunk's Rv (other buffer; becomes visible at phase-A barrier)
        if (t < 32 && n < 31)
            sm.Rv_s[rb ^ 1][t] = __ldg(&Rv_glob[(b * NN + j0 + 32 + t) * NH + h]);

        // adj prefetch: row il, 16 j (this thread's half)
        float4 av[4];
        const float4* ap = reinterpret_cast<const float4*>(
            adj + (size_t)(b * NN + i0 + il) * NN + j0 + jh * 16);
#pragma unroll
        for (int m = 0; m < 4; m++) av[m] = __ldg(&ap[m]);

        // g transpose staging: thread (jj = t>>3, d = (t&7)*4 .. +3)
        {
            int jj = t >> 3, dg = (t & 7) * 4;
            float4 gv = *reinterpret_cast<const float4*>(
                g_buf + (size_t)(b * NN + j0 + jj) * OUTF + h * 32 + dg);
            float vs[4] = {gv.x, gv.y, gv.z, gv.w};
#pragma unroll
            for (int e = 0; e < 4; e++) {
                uint32_t hb = f2tf32(vs[e]);
                float lo = vs[e] - __uint_as_float(hb);
                sm.G_hi[dg + e][jj] = __uint_as_float(hb);
                sm.G_lo[dg + e][jj] = __uint_as_float(f2tf32(lo));
            }
        }

        // weight tile: 16 weights (row il, j jh*16..+15) -> A_hi/A_lo
#pragma unroll
        for (int m4 = 0; m4 < 4; m4++) {
            float avv[4] = {av[m4].x, av[m4].y, av[m4].z, av[m4].w};
            float4 hi4, lo4;
            float* hp = &hi4.x; float* lp2 = &lo4.x;
#pragma unroll
            for (int e = 0; e < 4; e++) {
                float4 rv = sm.Rv_s[rb][jh * 16 + m4 * 4 + e];
                float p = Lp * rv.x;
                float q = Ln * rv.y;
                float wv = avv[e] * ((p >= rv.z) ? p : q);
                uint32_t hb = f2tf32(wv);
                float lo = wv - __uint_as_float(hb);
                hp[e] = __uint_as_float(hb);
                lp2[e] = __uint_as_float(f2tf32(lo));
            }
            *reinterpret_cast<float4*>(&sm.A_hi[il][jh * 16 + m4 * 4]) = hi4;
            *reinterpret_cast<float4*>(&sm.A_lo[il][jh * 16 + m4 * 4]) = lo4;
        }
        __syncthreads();

        // mma phase: 4 ksteps x 4 ntiles x 3 mma
#pragma unroll
        for (int k = 0; k < 4; k++) {
            const int kb = k * 8;
            uint32_t ah[4], al[4];
            ah[0] = __float_as_uint(sm.A_hi[m0 + gq][kb + tid4]);
            ah[1] = __float_as_uint(sm.A_hi[m0 + gq + 8][kb + tid4]);
            ah[2] = __float_as_uint(sm.A_hi[m0 + gq][kb + tid4 + 4]);
            ah[3] = __float_as_uint(sm.A_hi[m0 + gq + 8][kb + tid4 + 4]);
            al[0] = __float_as_uint(sm.A_lo[m0 + gq][kb + tid4]);
            al[1] = __float_as_uint(sm.A_lo[m0 + gq + 8][kb + tid4]);
            al[2] = __float_as_uint(sm.A_lo[m0 + gq][kb + tid4 + 4]);
            al[3] = __float_as_uint(sm.A_lo[m0 + gq + 8][kb + tid4 + 4]);
#pragma unroll
            for (int nt = 0; nt < 4; nt++) {
                const int nb = nt * 8;
                uint32_t bh[2], bl[2];
                bh[0] = __float_as_uint(sm.G_hi[nb + gq][kb + tid4]);
                bh[1] = __float_as_uint(sm.G_hi[nb + gq][kb + tid4 + 4]);
                bl[0] = __float_as_uint(sm.G_lo[nb + gq][kb + tid4]);
                bl[1] = __float_as_uint(sm.G_lo[nb + gq][kb + tid4 + 4]);
                mma_tf32(acc[nt], ah, bh);
                mma_tf32(acc[nt], ah, bl);
                mma_tf32(acc[nt], al, bh);
            }
        }
        __syncthreads();
    }

    // epilogue: D layout m16n8 -> rows m0+gq, m0+gq+8; cols nb + 2*tid4
#pragma unroll
    for (int nt = 0; nt < 4; nt++) {
        float* op0 = out + (size_t)(b * NN + i0 + m0 + gq) * OUTF + h * 32 + nt * 8 + 2 * tid4;
        float* op1 = op0 + 8 * OUTF;
        *reinterpret_cast<float2*>(op0) = make_float2(acc[nt][0], acc[nt][1]);
        *reinterpret_cast<float2*>(op1) = make_float2(acc[nt][2], acc[nt][3]);
    }
}

// ---------------------------------------------------------------------------
extern "C" void kernel_launch(void* const* d_in, const int* in_sizes, int n_in,
                              void* d_out, int out_size) {
    const float* h_in = (const float*)d_in[0];
    const float* adj  = (const float*)d_in[1];
    const float* W    = (const float*)d_in[2];
    const float* aw   = (const float*)d_in[3];
    float* out = (float*)d_out;

    k_gemm<<<256, 256>>>(h_in, W, aw);
    k_exp<<<BN * NH / 256, 256>>>();
    k_c<<<(BB * NN) / 32, 512>>>(adj);
    k_aggmma<<<256, 256>>>(adj, out);
}